// round 15
// baseline (speedup 1.0000x reference)
#include <cuda_runtime.h>
#include <cuda_fp16.h>
#include <stdint.h>
#include <math.h>

// Problem constants (fixed by the dataset)
#define BB 8
#define NV 500000
#define NF 1000000
#define VSTRIDE 32            // padded row: 24 used halfs + 8 pad = 64B (2 sectors)
#define NEPAD (6*NF + 8*NV + 4096)  // CSR capacity + pad-to-8 + overrun slack

#define SCAN_CHUNK 1024
#define SCAN_NB ((NV + SCAN_CHUNK - 1)/SCAN_CHUNK)   // 489

// ---- device-global scratch (no cudaMalloc allowed) ----
// row NV is the dummy zero row (never written -> stays zero across replays)
__device__ __align__(128) __half g_vt[(size_t)(NV+1)*VSTRIDE];  // [N+1][32] fp16 (32 MB)
__device__ int   g_deg[NV];              // true degree
__device__ int   g_off[NV];              // CSR offsets of PADDED degrees (multiples of 8)
__device__ int   g_cur[NV];              // fill cursors
__device__ __align__(16) int g_adj[NEPAD];  // CSR adjacency (segment tails garbage, masked)
__device__ int   g_fi[3*NF];             // faces converted to clamped int32
__device__ int   g_bsum[1024];           // scan block sums
__device__ float g_ct[(size_t)NV*BB];    // curvature, vertex-major [N][8]
__device__ int   g_is64;                 // faces dtype flag (1 = int64, 0 = int32)

// ---------------------------------------------------------------------------
// 0) dtype probe: int64 faces with values < 500000 have all odd words zero.
// ---------------------------------------------------------------------------
__global__ void k_probe(const int* __restrict__ f) {
    __shared__ int any;
    if (threadIdx.x == 0) any = 0;
    __syncthreads();
    int bad = 0;
    for (int i = threadIdx.x; i < 4096; i += blockDim.x)
        if (f[2*i + 1] != 0) bad = 1;
    if (bad) atomicOr(&any, 1);
    __syncthreads();
    if (threadIdx.x == 0) g_is64 = (any == 0);
}

__device__ __forceinline__ void load_face_raw(const void* faces, int f,
                                              int& i, int& j, int& k) {
    if (g_is64) {
        const long long* p = (const long long*)faces + (size_t)f * 3;
        i = (int)p[0]; j = (int)p[1]; k = (int)p[2];
    } else {
        const int* p = (const int*)faces + (size_t)f * 3;
        i = p[0]; j = p[1]; k = p[2];
    }
    i = min(max(i, 0), NV - 1);
    j = min(max(j, 0), NV - 1);
    k = min(max(k, 0), NV - 1);
}

// ---------------------------------------------------------------------------
// 1) vert (B,N,3) -> vt (N, 32-padded) fp16: element b*3+c.
//    Fused: zero g_deg.
// ---------------------------------------------------------------------------
__global__ void k_transpose(const float* __restrict__ vert) {
    __shared__ float s[64*24];
    int n0 = blockIdx.x * 64;
    int t  = threadIdx.x;                 // 192 threads

    int gi = blockIdx.x * 192 + t;        // fused degree zeroing
    if (gi < NV) g_deg[gi] = 0;

    int nrem = NV - n0; if (nrem > 64) nrem = 64;
    int cnt = nrem * 3;
    #pragma unroll
    for (int b = 0; b < 8; b++) {
        if (t < cnt) {
            int v = t / 3, c = t - v*3;
            s[v*24 + b*3 + c] = vert[(size_t)b*NV*3 + (size_t)n0*3 + t];
        }
    }
    __syncthreads();
    int tot = nrem * 24;
    for (int i = t; i < tot; i += 192) {
        int v = i / 24, e = i - v*24;
        g_vt[(size_t)(n0 + v)*VSTRIDE + e] = __float2half(s[i]);
    }
}

// ---------------------------------------------------------------------------
// 3) degree histogram + int32 face conversion (single faces pass)
// ---------------------------------------------------------------------------
__global__ void k_hist(const void* __restrict__ faces) {
    int f = blockIdx.x * blockDim.x + threadIdx.x;
    if (f >= NF) return;
    int i, j, k;
    load_face_raw(faces, f, i, j, k);
    size_t o = (size_t)f * 3;
    g_fi[o] = i; g_fi[o+1] = j; g_fi[o+2] = k;
    atomicAdd(&g_deg[i], 2);
    atomicAdd(&g_deg[j], 2);
    atomicAdd(&g_deg[k], 2);
}

// ---------------------------------------------------------------------------
// 4a) per-block sums of PADDED degrees ((deg+7)&~7) — warp-shuffle reduce.
// ---------------------------------------------------------------------------
__device__ __forceinline__ int pdeg_of(int i) {
    return (i < NV) ? ((g_deg[i] + 7) & ~7) : 0;
}

__global__ void k_scanA() {
    __shared__ int ws[32];
    int t    = threadIdx.x;               // 1024 threads
    int lane = t & 31;
    int warp = t >> 5;
    int v = pdeg_of(blockIdx.x * SCAN_CHUNK + t);
    #pragma unroll
    for (int d = 16; d > 0; d >>= 1)
        v += __shfl_down_sync(0xffffffffu, v, d);
    if (lane == 0) ws[warp] = v;
    __syncthreads();
    if (warp == 0) {
        int x = ws[lane];
        #pragma unroll
        for (int d = 16; d > 0; d >>= 1)
            x += __shfl_down_sync(0xffffffffu, x, d);
        if (lane == 0) g_bsum[blockIdx.x] = x;
    }
}

// ---------------------------------------------------------------------------
// 4b) final offsets — warp-shuffle scan (R14-proven).
// ---------------------------------------------------------------------------
__global__ void k_scanC() {
    __shared__ int rs[32];
    __shared__ int ws[32];
    __shared__ int sh_bpref;
    int t    = threadIdx.x;               // 1024 threads
    int lane = t & 31;
    int warp = t >> 5;

    int r = (t < blockIdx.x && t < SCAN_NB) ? g_bsum[t] : 0;
    #pragma unroll
    for (int d = 16; d > 0; d >>= 1)
        r += __shfl_down_sync(0xffffffffu, r, d);
    if (lane == 0) rs[warp] = r;

    int i  = blockIdx.x * SCAN_CHUNK + t;
    int pd = pdeg_of(i);
    int x  = pd;
    #pragma unroll
    for (int d = 1; d < 32; d <<= 1) {
        int y = __shfl_up_sync(0xffffffffu, x, d);
        if (lane >= d) x += y;
    }
    if (lane == 31) ws[warp] = x;
    __syncthreads();

    if (warp == 0) {
        int rr = rs[lane];
        #pragma unroll
        for (int d = 16; d > 0; d >>= 1)
            rr += __shfl_down_sync(0xffffffffu, rr, d);
        if (lane == 0) sh_bpref = rr;
        int w = ws[lane];
        int xs = w;
        #pragma unroll
        for (int d = 1; d < 32; d <<= 1) {
            int y = __shfl_up_sync(0xffffffffu, xs, d);
            if (lane >= d) xs += y;
        }
        ws[lane] = xs - w;
    }
    __syncthreads();

    int ex = (x - pd) + ws[warp] + sh_bpref;
    if (i < NV) { g_off[i] = ex; g_cur[i] = ex; }
}

// ---------------------------------------------------------------------------
// 5) CSR fill: per face, append the 2 neighbors of each corner (int2 stores)
// ---------------------------------------------------------------------------
__global__ void k_fill() {
    int f = blockIdx.x * blockDim.x + threadIdx.x;
    if (f >= NF) return;
    size_t o = (size_t)f * 3;
    int i = g_fi[o], j = g_fi[o+1], k = g_fi[o+2];
    int p;
    p = atomicAdd(&g_cur[i], 2); *(int2*)&g_adj[p] = make_int2(j, k);
    p = atomicAdd(&g_cur[j], 2); *(int2*)&g_adj[p] = make_int2(i, k);
    p = atomicAdd(&g_cur[k], 2); *(int2*)&g_adj[p] = make_int2(i, j);
}

// ---------------------------------------------------------------------------
// 6) gather + curvature: TWO vertices per warp, branchless interleaved
//    load streams (4 adj int4 + 16 masked vt loads per iteration, single
//    basic block -> ~20 loads in flight per warp). Lane e<24 owns element
//    b*3+c. Out-of-range groups masked to the L1-hot dummy zero row NV.
// ---------------------------------------------------------------------------
__global__ void k_gather() {
    int w    = (blockIdx.x * blockDim.x + threadIdx.x) >> 5;
    int lane = threadIdx.x & 31;
    int v0 = 2*w, v1 = 2*w + 1;
    if (v1 >= NV) return;                 // grid exact; harmless guard

    int s0 = g_off[v0], d0 = g_deg[v0], e0 = s0 + d0;
    int s1 = g_off[v1], d1 = g_deg[v1], e1 = s1 + d1;
    int it = max((d0 + 7) >> 3, (d1 + 7) >> 3);

    bool act = lane < 24;
    float own0 = 0.f, own1 = 0.f, acc0 = 0.f, acc1 = 0.f;
    if (act) {
        own0 = __half2float(__ldg(&g_vt[(size_t)v0*VSTRIDE + lane]));
        own1 = __half2float(__ldg(&g_vt[(size_t)v1*VSTRIDE + lane]));
    }

    for (int k = 0; k < it; k++) {
        int b0 = s0 + k*8, b1 = s1 + k*8;
        int4 p0 = __ldg((const int4*)&g_adj[b0]);
        int4 p1 = __ldg((const int4*)&g_adj[b0 + 4]);
        int4 q0 = __ldg((const int4*)&g_adj[b1]);
        int4 q1 = __ldg((const int4*)&g_adj[b1 + 4]);
        int a0 = (b0 + 0 < e0) ? p0.x : NV;
        int a1 = (b0 + 1 < e0) ? p0.y : NV;
        int a2 = (b0 + 2 < e0) ? p0.z : NV;
        int a3 = (b0 + 3 < e0) ? p0.w : NV;
        int a4 = (b0 + 4 < e0) ? p1.x : NV;
        int a5 = (b0 + 5 < e0) ? p1.y : NV;
        int a6 = (b0 + 6 < e0) ? p1.z : NV;
        int a7 = (b0 + 7 < e0) ? p1.w : NV;
        int c0 = (b1 + 0 < e1) ? q0.x : NV;
        int c1 = (b1 + 1 < e1) ? q0.y : NV;
        int c2 = (b1 + 2 < e1) ? q0.z : NV;
        int c3 = (b1 + 3 < e1) ? q0.w : NV;
        int c4 = (b1 + 4 < e1) ? q1.x : NV;
        int c5 = (b1 + 5 < e1) ? q1.y : NV;
        int c6 = (b1 + 6 < e1) ? q1.z : NV;
        int c7 = (b1 + 7 < e1) ? q1.w : NV;
        if (act) {
            float t0 = __half2float(__ldg(&g_vt[(size_t)a0*VSTRIDE + lane]));
            float t1 = __half2float(__ldg(&g_vt[(size_t)a1*VSTRIDE + lane]));
            float t2 = __half2float(__ldg(&g_vt[(size_t)a2*VSTRIDE + lane]));
            float t3 = __half2float(__ldg(&g_vt[(size_t)a3*VSTRIDE + lane]));
            float t4 = __half2float(__ldg(&g_vt[(size_t)a4*VSTRIDE + lane]));
            float t5 = __half2float(__ldg(&g_vt[(size_t)a5*VSTRIDE + lane]));
            float t6 = __half2float(__ldg(&g_vt[(size_t)a6*VSTRIDE + lane]));
            float t7 = __half2float(__ldg(&g_vt[(size_t)a7*VSTRIDE + lane]));
            float u0 = __half2float(__ldg(&g_vt[(size_t)c0*VSTRIDE + lane]));
            float u1 = __half2float(__ldg(&g_vt[(size_t)c1*VSTRIDE + lane]));
            float u2 = __half2float(__ldg(&g_vt[(size_t)c2*VSTRIDE + lane]));
            float u3 = __half2float(__ldg(&g_vt[(size_t)c3*VSTRIDE + lane]));
            float u4 = __half2float(__ldg(&g_vt[(size_t)c4*VSTRIDE + lane]));
            float u5 = __half2float(__ldg(&g_vt[(size_t)c5*VSTRIDE + lane]));
            float u6 = __half2float(__ldg(&g_vt[(size_t)c6*VSTRIDE + lane]));
            float u7 = __half2float(__ldg(&g_vt[(size_t)c7*VSTRIDE + lane]));
            acc0 += ((t0 + t1) + (t2 + t3)) + ((t4 + t5) + (t6 + t7));
            acc1 += ((u0 + u1) + (u2 + u3)) + ((u4 + u5) + (u6 + u7));
        }
    }

    float inv0 = 1.f / fmaxf((float)d0, 1.f);
    float inv1 = 1.f / fmaxf((float)d1, 1.f);
    float lap0 = acc0 * inv0 - own0;
    float lap1 = acc1 * inv1 - own1;
    float sq0  = lap0 * lap0;
    float sq1  = lap1 * lap1;
    float x1 = __shfl_down_sync(0xffffffffu, sq0, 1);
    float x2 = __shfl_down_sync(0xffffffffu, sq0, 2);
    float y1 = __shfl_down_sync(0xffffffffu, sq1, 1);
    float y2 = __shfl_down_sync(0xffffffffu, sq1, 2);
    float sum0 = sq0 + x1 + x2;
    float sum1 = sq1 + y1 + y2;
    if (act && (lane % 3) == 0) {
        g_ct[(size_t)v0*8 + lane/3] = sqrtf(sum0);
        g_ct[(size_t)v1*8 + lane/3] = sqrtf(sum1);
    }
}

// ---------------------------------------------------------------------------
// 7) output transpose: g_ct [N][8] -> out [8][N]
// ---------------------------------------------------------------------------
__global__ void k_outT(float* __restrict__ out) {
    __shared__ float s[32*9];             // pad 8->9 to kill bank conflicts
    int n0 = blockIdx.x * 32;
    int t  = threadIdx.x;                 // 256 threads
    {
        int v = t >> 3, e = t & 7;
        s[v*9 + e] = g_ct[(size_t)n0*8 + t];   // coalesced 1KB read
    }
    __syncthreads();
    int b = t >> 5, v = t & 31;
    out[(size_t)b*NV + n0 + v] = s[v*9 + b];   // coalesced 128B per batch row
}

// ---------------------------------------------------------------------------
extern "C" void kernel_launch(void* const* d_in, const int* in_sizes, int n_in,
                              void* d_out, int out_size) {
    const float* vert  = (const float*)d_in[0];   // (8, 500000, 3) f32
    const void*  faces = d_in[1];                 // (1000000, 3) i64 OR i32
    float* out = (float*)d_out;                   // (8, 500000) f32

    // 0) detect faces dtype
    k_probe<<<1, 256>>>((const int*)faces);
    // 1) transpose vertices into padded fp16 [N][32] (+ fused degree zeroing)
    k_transpose<<<(NV + 63) / 64, 192>>>(vert);
    // 3) degree histogram + int32 conversion
    k_hist<<<(NF + 255) / 256, 256>>>(faces);
    // 4) scan of padded degrees -> aligned CSR offsets (warp-shuffle scans)
    k_scanA<<<SCAN_NB, SCAN_CHUNK>>>();
    k_scanC<<<SCAN_NB, SCAN_CHUNK>>>();
    // 5) CSR fill (int32 faces, int2 stores)
    k_fill<<<(NF + 255) / 256, 256>>>();
    // 6) gather + curvature (2 vertices/warp, branchless interleaved)
    k_gather<<<NV / 16, 256>>>();
    // 7) output transpose
    k_outT<<<NV / 32, 256>>>(out);
}